// round 15
// baseline (speedup 1.0000x reference)
#include <cuda_runtime.h>

// QuantizedLinear(5 -> 10, bits=2) over 4M tokens, fp32.
//
// Pure streaming kernel, no smem staging, no TMA, no per-tile syncs.
// Slot s <-> (token p = s/5, j = s%5); thread computes outputs {2j, 2j+1}
// of token p. Store addresses 40p+8j are perfectly contiguous across a warp
// -> one dense STG.64 (256B/warp). Grid-stride with stride % 5 == 0 keeps j
// constant per thread, so the 12 dequantized weights live in registers,
// loaded once after a single per-block dequant (threads 0..9).

#define THREADS 256
#define ROUNDS 8
#define IN_F 5
#define OUT_F 10

__global__ __launch_bounds__(THREADS)
void qlinear2bit_kernel(const float* __restrict__ x,
                        const float* __restrict__ w,
                        const float* __restrict__ bias,
                        float* __restrict__ out,
                        long long slots)          // 5 * n_tokens
{
    __shared__ float sw[OUT_F * IN_F];
    __shared__ float sb[OUT_F];

    const int t = threadIdx.x;

    // ---- dequantize weights once per block (threads 0..9) ----
    if (t < OUT_F) {
        float r[IN_F];
        float m = 0.0f;
        #pragma unroll
        for (int c = 0; c < IN_F; c++) {
            r[c] = w[t * IN_F + c];
            m = fmaxf(m, fabsf(r[c]));
        }
        float scale = fmaxf(m, 1e-8f);          // qmax = 2^(bits-1)-1 = 1
        float inv = 1.0f / scale;
        #pragma unroll
        for (int c = 0; c < IN_F; c++) {
            float q = rintf(r[c] * inv);        // round-half-to-even == jnp.round
            sw[t * IN_F + c] = fminf(fmaxf(q, -2.0f), 1.0f) * scale;
        }
        sb[t] = bias[t];
    }
    __syncthreads();

    long long s = (long long)blockIdx.x * THREADS + t;
    const int j = (int)(s % 5);                 // constant across rounds

    // ---- this thread's 2 weight rows + biases into registers ----
    float wd[2][IN_F], b2[2];
    #pragma unroll
    for (int r = 0; r < 2; r++) {
        const int o = 2 * j + r;
        #pragma unroll
        for (int c = 0; c < IN_F; c++) wd[r][c] = sw[o * IN_F + c];
        b2[r] = sb[o];
    }

    const long long stride = (long long)gridDim.x * THREADS;  // % 5 == 0
    long long p = s / 5;
    const float* px = x + p * IN_F;
    float*       po = out + p * OUT_F + 2 * j;

    #pragma unroll
    for (int r = 0; r < ROUNDS; r++) {
        if (s < slots) {
            const float x0 = px[0], x1 = px[1], x2 = px[2],
                        x3 = px[3], x4 = px[4];
            float a0 = b2[0];
            a0 = fmaf(x0, wd[0][0], a0);
            a0 = fmaf(x1, wd[0][1], a0);
            a0 = fmaf(x2, wd[0][2], a0);
            a0 = fmaf(x3, wd[0][3], a0);
            a0 = fmaf(x4, wd[0][4], a0);
            float a1 = b2[1];
            a1 = fmaf(x0, wd[1][0], a1);
            a1 = fmaf(x1, wd[1][1], a1);
            a1 = fmaf(x2, wd[1][2], a1);
            a1 = fmaf(x3, wd[1][3], a1);
            a1 = fmaf(x4, wd[1][4], a1);
            *reinterpret_cast<float2*>(po) = make_float2(a0, a1);  // STG.64
        }
        s  += stride;
        px += stride;           // stride slots -> stride/5 tokens * 5 floats
        po += stride * 2;       // stride/5 tokens * 10 floats
    }
}

extern "C" void kernel_launch(void* const* d_in, const int* in_sizes, int n_in,
                              void* d_out, int out_size)
{
    const float* x    = (const float*)d_in[0];   // [N, 5]
    const float* w    = (const float*)d_in[1];   // [10, 5]
    const float* bias = (const float*)d_in[2];   // [10]
    float* out = (float*)d_out;                  // [N, 10]

    const int n_tokens = in_sizes[0] / IN_F;
    const long long slots = 5LL * n_tokens;
    long long g = (slots + (long long)THREADS * ROUNDS - 1)
                  / ((long long)THREADS * ROUNDS);
    g = ((g + 4) / 5) * 5;                       // stride % 5 == 0 -> j stable
    qlinear2bit_kernel<<<(int)g, THREADS>>>(x, w, bias, out, slots);
}

// round 16
// speedup vs baseline: 1.0029x; 1.0029x over previous
#include <cuda_runtime.h>

// QuantizedLinear(5 -> 10, bits=2) over 4M tokens, fp32.
//
// Pure streaming kernel, no smem staging, no TMA, no per-tile syncs.
// Slot s <-> (token p = s/5, j = s%5); thread computes outputs {2j, 2j+1}
// of token p. Store addresses 40p+8j are perfectly contiguous across a warp
// -> one dense STG.64 (256B/warp). Grid-stride with stride % 5 == 0 keeps j
// constant per thread, so the 12 dequantized weights live in registers,
// loaded once after a single per-block dequant (threads 0..9).

#define THREADS 256
#define ROUNDS 8
#define IN_F 5
#define OUT_F 10

__global__ __launch_bounds__(THREADS)
void qlinear2bit_kernel(const float* __restrict__ x,
                        const float* __restrict__ w,
                        const float* __restrict__ bias,
                        float* __restrict__ out,
                        long long slots)          // 5 * n_tokens
{
    __shared__ float sw[OUT_F * IN_F];
    __shared__ float sb[OUT_F];

    const int t = threadIdx.x;

    // ---- dequantize weights once per block (threads 0..9) ----
    if (t < OUT_F) {
        float r[IN_F];
        float m = 0.0f;
        #pragma unroll
        for (int c = 0; c < IN_F; c++) {
            r[c] = w[t * IN_F + c];
            m = fmaxf(m, fabsf(r[c]));
        }
        float scale = fmaxf(m, 1e-8f);          // qmax = 2^(bits-1)-1 = 1
        float inv = 1.0f / scale;
        #pragma unroll
        for (int c = 0; c < IN_F; c++) {
            float q = rintf(r[c] * inv);        // round-half-to-even == jnp.round
            sw[t * IN_F + c] = fminf(fmaxf(q, -2.0f), 1.0f) * scale;
        }
        sb[t] = bias[t];
    }
    __syncthreads();

    long long s = (long long)blockIdx.x * THREADS + t;
    const int j = (int)(s % 5);                 // constant across rounds

    // ---- this thread's 2 weight rows + biases into registers ----
    float wd[2][IN_F], b2[2];
    #pragma unroll
    for (int r = 0; r < 2; r++) {
        const int o = 2 * j + r;
        #pragma unroll
        for (int c = 0; c < IN_F; c++) wd[r][c] = sw[o * IN_F + c];
        b2[r] = sb[o];
    }

    const long long stride = (long long)gridDim.x * THREADS;  // % 5 == 0
    long long p = s / 5;
    const float* px = x + p * IN_F;
    float*       po = out + p * OUT_F + 2 * j;

    #pragma unroll
    for (int r = 0; r < ROUNDS; r++) {
        if (s < slots) {
            const float x0 = px[0], x1 = px[1], x2 = px[2],
                        x3 = px[3], x4 = px[4];
            float a0 = b2[0];
            a0 = fmaf(x0, wd[0][0], a0);
            a0 = fmaf(x1, wd[0][1], a0);
            a0 = fmaf(x2, wd[0][2], a0);
            a0 = fmaf(x3, wd[0][3], a0);
            a0 = fmaf(x4, wd[0][4], a0);
            float a1 = b2[1];
            a1 = fmaf(x0, wd[1][0], a1);
            a1 = fmaf(x1, wd[1][1], a1);
            a1 = fmaf(x2, wd[1][2], a1);
            a1 = fmaf(x3, wd[1][3], a1);
            a1 = fmaf(x4, wd[1][4], a1);
            *reinterpret_cast<float2*>(po) = make_float2(a0, a1);  // STG.64
        }
        s  += stride;
        px += stride;           // stride slots -> stride/5 tokens * 5 floats
        po += stride * 2;       // stride/5 tokens * 10 floats
    }
}

extern "C" void kernel_launch(void* const* d_in, const int* in_sizes, int n_in,
                              void* d_out, int out_size)
{
    const float* x    = (const float*)d_in[0];   // [N, 5]
    const float* w    = (const float*)d_in[1];   // [10, 5]
    const float* bias = (const float*)d_in[2];   // [10]
    float* out = (float*)d_out;                  // [N, 10]

    const int n_tokens = in_sizes[0] / IN_F;
    const long long slots = 5LL * n_tokens;
    long long g = (slots + (long long)THREADS * ROUNDS - 1)
                  / ((long long)THREADS * ROUNDS);
    g = ((g + 4) / 5) * 5;                       // stride % 5 == 0 -> j stable
    qlinear2bit_kernel<<<(int)g, THREADS>>>(x, w, bias, out, slots);
}

// round 17
// speedup vs baseline: 1.3326x; 1.3287x over previous
#include <cuda_runtime.h>
#include <cstdint>

// QuantizedLinear(5 -> 10, bits=2) over 4M tokens, fp32.
//
// Hybrid of the two proven-best halves:
//  IN : 2-stage double-buffered 1D TMA loads of 256-token x tiles (keeps the
//       input stream off the L1 pipe and at R12/R13's DRAM efficiency).
//  OUT: dense STG.64 directly from registers (R16's slot mapping j = t%5,
//       THREADS=320 so j is round-invariant): warp stores are perfectly
//       contiguous 256 B. No output smem, no bulk-store drain -> the block's
//       serial chain is just load-wait -> compute.
// 4 tiles/block, 1 syncthreads per tile, ~11 KB smem, ~32 regs, 6 blocks/SM.

#define THREADS 320
#define TILE 256                  // tokens per tile
#define NT 4                      // tiles per block
#define NS 2                      // pipeline stages
#define IN_F 5
#define OUT_F 10
#define XB (TILE * IN_F * 4)      // 5120 B

#define MBAR_WAIT(mbaddr, ph) do {                                          \
    uint32_t _done;                                                         \
    asm volatile(                                                           \
        "{\n\t.reg .pred pq;\n\t"                                           \
        "mbarrier.try_wait.parity.acquire.cta.shared::cta.b64 pq, [%1], %2;\n\t" \
        "selp.b32 %0, 1, 0, pq;\n\t}"                                       \
        : "=r"(_done) : "r"(mbaddr), "r"(ph) : "memory");                   \
    if (!_done) {                                                           \
        asm volatile(                                                       \
            "{\n\t.reg .pred P1;\n\t"                                       \
            "W_%=:\n\t"                                                     \
            "mbarrier.try_wait.parity.acquire.cta.shared::cta.b64 P1, [%0], %1, 0x989680;\n\t" \
            "@P1 bra.uni D_%=;\n\t"                                         \
            "bra.uni W_%=;\n\t"                                             \
            "D_%=:\n\t}"                                                    \
            :: "r"(mbaddr), "r"(ph) : "memory");                            \
    }                                                                       \
} while (0)

__global__ __launch_bounds__(THREADS)
void qlinear2bit_kernel(const float* __restrict__ x,
                        const float* __restrict__ w,
                        const float* __restrict__ bias,
                        float* __restrict__ out,
                        int n_tokens)
{
    __shared__ __align__(128) float sx[NS][TILE * IN_F];   // 2 x 5 KB
    __shared__ float sw[OUT_F * IN_F];
    __shared__ float sb[OUT_F];
    __shared__ __align__(8) unsigned long long mbar[NS];

    const int t = threadIdx.x;
    const long long tok0 = (long long)blockIdx.x * (TILE * NT);
    const long long N = n_tokens;

    uint32_t mb[NS];
    #pragma unroll
    for (int s = 0; s < NS; s++)
        mb[s] = (uint32_t)__cvta_generic_to_shared(&mbar[s]);

    // ---- prologue: init mbarriers, issue loads for tiles 0..NS-1 ----
    if (t == 0) {
        #pragma unroll
        for (int s = 0; s < NS; s++)
            asm volatile("mbarrier.init.shared.b64 [%0], 1;" :: "r"(mb[s]));
        asm volatile("fence.proxy.async.shared::cta;" ::: "memory");
        #pragma unroll
        for (int k = 0; k < NS; k++) {
            const long long ts = tok0 + (long long)k * TILE;
            if (ts + TILE <= N) {
                const uint32_t dst = (uint32_t)__cvta_generic_to_shared(sx[k]);
                asm volatile("mbarrier.arrive.expect_tx.shared.b64 _, [%0], %1;"
                             :: "r"(mb[k]), "r"((uint32_t)XB));
                asm volatile(
                    "cp.async.bulk.shared::cluster.global.mbarrier::complete_tx::bytes "
                    "[%0], [%1], %2, [%3];"
                    :: "r"(dst), "l"(x + ts * IN_F), "r"((uint32_t)XB), "r"(mb[k])
                    : "memory");
            }
        }
    }

    // ---- dequantize weights once per block (threads 0..9) ----
    if (t < OUT_F) {
        float r[IN_F];
        float m = 0.0f;
        #pragma unroll
        for (int c = 0; c < IN_F; c++) {
            r[c] = w[t * IN_F + c];
            m = fmaxf(m, fabsf(r[c]));
        }
        float scale = fmaxf(m, 1e-8f);          // qmax = 2^(bits-1)-1 = 1
        float inv = 1.0f / scale;
        #pragma unroll
        for (int c = 0; c < IN_F; c++) {
            float q = rintf(r[c] * inv);        // round-half-to-even == jnp.round
            sw[t * IN_F + c] = fminf(fmaxf(q, -2.0f), 1.0f) * scale;
        }
        sb[t] = bias[t];
    }
    __syncthreads();    // mbarrier inits + sw/sb visible

    // ---- per-thread weights: outputs {2j, 2j+1}, j = t % 5 (round-stable) ----
    const int j = t % 5;
    const int q = t / 5;        // token slot within a round (0..63)
    float wd[2][IN_F], b2[2];
    #pragma unroll
    for (int r = 0; r < 2; r++) {
        const int o = 2 * j + r;
        #pragma unroll
        for (int c = 0; c < IN_F; c++) wd[r][c] = sw[o * IN_F + c];
        b2[r] = sb[o];
    }

    // ---- pipelined tiles: TMA in, dense STG.64 out ----
    for (int i = 0; i < NT; i++) {
        const long long ts = tok0 + (long long)i * TILE;
        if (ts >= N) break;
        const int s = i % NS;
        const uint32_t ph = (uint32_t)((i / NS) & 1);
        const bool full = (ts + TILE <= N);

        if (full) {
            MBAR_WAIT(mb[s], ph);               // x tile i ready
            #pragma unroll
            for (int r = 0; r < TILE / 64; r++) {
                const int p = r * 64 + q;       // token within tile
                float xi[IN_F];
                #pragma unroll
                for (int c = 0; c < IN_F; c++)
                    xi[c] = sx[s][p * IN_F + c];     // 5-lane multicast LDS
                float a0 = b2[0], a1 = b2[1];
                #pragma unroll
                for (int c = 0; c < IN_F; c++) {
                    a0 = fmaf(xi[c], wd[0][c], a0);
                    a1 = fmaf(xi[c], wd[1][c], a1);
                }
                // warp-contiguous: addr = 40*(ts+p) + 8j, step 8 B per lane
                *reinterpret_cast<float2*>(out + (ts + p) * OUT_F + 2 * j) =
                    make_float2(a0, a1);             // dense STG.64
            }
            __syncthreads();                    // sx[s] fully consumed

            // reissue stage s for tile i+NS
            const long long nts = tok0 + (long long)(i + NS) * TILE;
            if (t == 0 && i + NS < NT && nts + TILE <= N) {
                const uint32_t dst = (uint32_t)__cvta_generic_to_shared(sx[s]);
                asm volatile("mbarrier.arrive.expect_tx.shared.b64 _, [%0], %1;"
                             :: "r"(mb[s]), "r"((uint32_t)XB));
                asm volatile(
                    "cp.async.bulk.shared::cluster.global.mbarrier::complete_tx::bytes "
                    "[%0], [%1], %2, [%3];"
                    :: "r"(dst), "l"(x + nts * IN_F), "r"((uint32_t)XB),
                       "r"(mb[s])
                    : "memory");
            }
        } else {
            // partial tile: guarded direct-gmem path
            #pragma unroll
            for (int r = 0; r < TILE / 64; r++) {
                const long long gtok = ts + r * 64 + q;
                if (gtok < N) {
                    float xi[IN_F];
                    #pragma unroll
                    for (int c = 0; c < IN_F; c++)
                        xi[c] = x[gtok * IN_F + c];
                    float a0 = b2[0], a1 = b2[1];
                    #pragma unroll
                    for (int c = 0; c < IN_F; c++) {
                        a0 = fmaf(xi[c], wd[0][c], a0);
                        a1 = fmaf(xi[c], wd[1][c], a1);
                    }
                    *reinterpret_cast<float2*>(out + gtok * OUT_F + 2 * j) =
                        make_float2(a0, a1);
                }
            }
        }
    }
}

extern "C" void kernel_launch(void* const* d_in, const int* in_sizes, int n_in,
                              void* d_out, int out_size)
{
    const float* x    = (const float*)d_in[0];   // [N, 5]
    const float* w    = (const float*)d_in[1];   // [10, 5]
    const float* bias = (const float*)d_in[2];   // [10]
    float* out = (float*)d_out;                  // [N, 10]

    const int n_tokens = in_sizes[0] / IN_F;
    const int tokens_per_block = TILE * NT;
    const int grid = (n_tokens + tokens_per_block - 1) / tokens_per_block;
    qlinear2bit_kernel<<<grid, THREADS>>>(x, w, bias, out, n_tokens);
}